// round 6
// baseline (speedup 1.0000x reference)
#include <cuda_runtime.h>
#include <cstdint>

#define QKV_SZ (512u * 8u * 64u * 64u)
// Scratch (device globals; no runtime allocation).
__device__ __align__(16) uint32_t g_qkv[3 * QKV_SZ];     // tf32 bits, [which][bw][h][t][d]
__device__ __align__(16) uint32_t g_xtf[32768u * 512u];  // x as tf32(RNA) bits
__device__ __align__(16) uint32_t g_wtf[1536u * 512u];   // Wq|Wk|Wv as tf32 bits

__device__ __forceinline__ uint32_t f2tf(float f) {
    uint32_t u;
    asm("cvt.rna.tf32.f32 %0, %1;" : "=r"(u) : "f"(f));
    return u;
}

__device__ __forceinline__ void mma_tf32(float c[4], const uint32_t a[4], const uint32_t b[2]) {
    asm volatile(
        "mma.sync.aligned.m16n8k8.row.col.f32.tf32.tf32.f32 "
        "{%0,%1,%2,%3}, {%4,%5,%6,%7}, {%8,%9}, {%0,%1,%2,%3};"
        : "+f"(c[0]), "+f"(c[1]), "+f"(c[2]), "+f"(c[3])
        : "r"(a[0]), "r"(a[1]), "r"(a[2]), "r"(a[3]), "r"(b[0]), "r"(b[1]));
}

// ---- mbarrier + bulk-copy helpers (sm_90 baseline; compiled OK on sm_100) ----
__device__ __forceinline__ void mbar_init(uint32_t addr, uint32_t count) {
    asm volatile("mbarrier.init.shared.b64 [%0], %1;" :: "r"(addr), "r"(count) : "memory");
}
__device__ __forceinline__ void mbar_expect_tx(uint32_t addr, uint32_t bytes) {
    asm volatile("mbarrier.arrive.expect_tx.shared.b64 _, [%0], %1;"
                 :: "r"(addr), "r"(bytes) : "memory");
}
__device__ __forceinline__ void mbar_wait(uint32_t addr, uint32_t parity) {
    uint32_t done;
    asm volatile(
        "{\n\t.reg .pred p;\n\t"
        "mbarrier.try_wait.parity.acquire.cta.shared::cta.b64 p, [%1], %2;\n\t"
        "selp.b32 %0, 1, 0, p;\n\t}"
        : "=r"(done) : "r"(addr), "r"(parity) : "memory");
    if (!done) {
        asm volatile(
            "{\n\t.reg .pred P1;\n\t"
            "WL_%=:\n\t"
            "mbarrier.try_wait.parity.acquire.cta.shared::cta.b64 P1, [%0], %1, 0x989680;\n\t"
            "@P1 bra.uni WD_%=;\n\t"
            "bra.uni WL_%=;\n\t"
            "WD_%=:\n\t}"
            :: "r"(addr), "r"(parity) : "memory");
    }
}
__device__ __forceinline__ void bulk_g2s(uint32_t dst, const void* src, uint32_t bytes,
                                         uint32_t mbar) {
    asm volatile(
        "cp.async.bulk.shared::cta.global.mbarrier::complete_tx::bytes [%0], [%1], %2, [%3];"
        :: "r"(dst), "l"(src), "r"(bytes), "r"(mbar) : "memory");
}

// ---------------------------------------------------------------------------
// Pre-convert kernels: fp32 -> tf32(RNA) bits, 16B vectorized.
// ---------------------------------------------------------------------------
__global__ void __launch_bounds__(256) conv_x_kernel(const float* __restrict__ x)
{
    const int i = blockIdx.x * 256 + threadIdx.x;
    float4 v = ((const float4*)x)[i];
    ((uint4*)g_xtf)[i] = make_uint4(f2tf(v.x), f2tf(v.y), f2tf(v.z), f2tf(v.w));
}

__global__ void __launch_bounds__(256) conv_w_kernel(
    const float* __restrict__ Wq, const float* __restrict__ Wk, const float* __restrict__ Wv)
{
    const int i = blockIdx.x * 256 + threadIdx.x;
    const int which = i >> 16;
    const int sub = i & 65535;
    const float* W = (which == 0) ? Wq : (which == 1) ? Wk : Wv;
    float4 v = ((const float4*)W)[sub];
    ((uint4*)g_wtf)[i] = make_uint4(f2tf(v.x), f2tf(v.y), f2tf(v.z), f2tf(v.w));
}

// ---------------------------------------------------------------------------
// Kernel A: QKV projection via legacy tf32 mma, bulk-copy staged smem.
// y[m,n] = sum_k x[m,k]*W[n,k] + b[n].  M=32768, N=1536, K=512.
// CTA tile 256x128, 256 threads (8 warps, 64x64 warp tiles).
// K chunked by 32 (128B rows). 3-stage pipeline: cp.async.bulk rows ->
// mbarrier complete_tx; stage recycled after compute __syncthreads.
// Grid (12, 128): blockIdx.x = N-tile (fast) -> x reused across N via L2.
// ---------------------------------------------------------------------------
#define KC 32
#define SPITCH_B 160                     // bytes per staged row (128 data + 32 pad)
#define SPITCH_W 40                      // words
#define ROWS_STG 384                     // 256 A rows + 128 B rows
#define STAGE_B (ROWS_STG * SPITCH_B)    // 61440
#define NSTAGE 3
#define PROJ_SMEM (NSTAGE * STAGE_B)     // 184320
#define TX_BYTES (ROWS_STG * 128)        // 49152 per stage

__global__ void __launch_bounds__(256) qkv_proj_kernel(
    const float* __restrict__ bq, const float* __restrict__ bk, const float* __restrict__ bv)
{
    extern __shared__ uint8_t dsm[];
    __shared__ __align__(8) uint64_t mbar[NSTAGE];

    const int tid  = threadIdx.x;
    const int warp = tid >> 5, lane = tid & 31;
    const int g = lane >> 2, tig = lane & 3;
    const int wm = (warp >> 1) * 64;     // 4x2 warp grid of 64x64 tiles
    const int wn = (warp & 1) * 64;

    const int nb = blockIdx.x * 128;     // 0..1408 in concatenated N
    const int mb = blockIdx.y * 256;
    const int which = nb >> 9;
    const int nw0 = nb & 511;
    const float* __restrict__ bias = (which == 0) ? bq : (which == 1) ? bk : bv;
    uint32_t* __restrict__ dst = g_qkv + (size_t)which * QKV_SZ;

    const uint32_t smem_base = (uint32_t)__cvta_generic_to_shared(dsm);
    const uint32_t mbar_base = (uint32_t)__cvta_generic_to_shared(mbar);

    if (tid == 0) {
#pragma unroll
        for (int s = 0; s < NSTAGE; s++) mbar_init(mbar_base + s * 8, 1);
    }
    __syncthreads();

    // Issue chunk c into stage c%3. 384 rows of 128B; threads 0..255 row tid,
    // threads 0..127 also row 256+tid (B rows).
    auto issue = [&](int c) {
        const int s = c % NSTAGE;
        const uint32_t mb_addr = mbar_base + s * 8;
        const uint32_t sbase = smem_base + (uint32_t)(s * STAGE_B);
        const int kel = c * KC;
        if (tid == 0) mbar_expect_tx(mb_addr, TX_BYTES);
        {   // A row tid
            const int r = tid;
            bulk_g2s(sbase + (uint32_t)r * SPITCH_B,
                     g_xtf + (size_t)(mb + r) * 512 + kel, 128, mb_addr);
        }
        if (tid < 128) {  // B row tid
            const int r = tid;
            bulk_g2s(sbase + (uint32_t)(256 + r) * SPITCH_B,
                     g_wtf + (size_t)(nb + r) * 512 + kel, 128, mb_addr);
        }
    };

    float acc[4][8][4];
#pragma unroll
    for (int i = 0; i < 4; i++)
#pragma unroll
        for (int j = 0; j < 8; j++)
#pragma unroll
            for (int c = 0; c < 4; c++) acc[i][j][c] = 0.f;

    issue(0);
    issue(1);

    for (int c = 0; c < 16; c++) {
        if (c + 2 < 16) issue(c + 2);    // stage (c+2)%3 freed by prev-iter syncthreads
        mbar_wait(mbar_base + (c % NSTAGE) * 8, (c / NSTAGE) & 1);

        const uint32_t* A = (const uint32_t*)(dsm + (c % NSTAGE) * STAGE_B);
        const uint32_t* B = A + 256 * SPITCH_W;

#pragma unroll
        for (int k8 = 0; k8 < 4; k8++) {
            uint32_t a[4][4];
#pragma unroll
            for (int i = 0; i < 4; i++) {
                const int r0 = (wm + i * 16 + g) * SPITCH_W + k8 * 8 + tig;
                a[i][0] = A[r0];
                a[i][1] = A[r0 + 8 * SPITCH_W];
                a[i][2] = A[r0 + 4];
                a[i][3] = A[r0 + 8 * SPITCH_W + 4];
            }
#pragma unroll
            for (int j = 0; j < 8; j++) {
                const int rb = (wn + j * 8 + g) * SPITCH_W + k8 * 8 + tig;
                uint32_t b[2];
                b[0] = B[rb];
                b[1] = B[rb + 4];
#pragma unroll
                for (int i = 0; i < 4; i++) mma_tf32(acc[i][j], a[i], b);
            }
        }
        __syncthreads();                 // all warps done reading this stage
    }

    // Epilogue: bias add (fp32), convert to tf32 bits, scatter [bw][h][t][d].
#pragma unroll
    for (int i = 0; i < 4; i++) {
        const int m0 = mb + wm + i * 16 + g;
#pragma unroll
        for (int j = 0; j < 8; j++) {
            const int col = nw0 + wn + j * 8 + tig * 2;   // within this matrix
            const float bv0 = bias[col], bv1 = bias[col + 1];
            const int h = col >> 6, d = col & 63;
            {
                const int m = m0;
                size_t o = (((size_t)(m >> 6) * 8 + h) * 64 + (m & 63)) * 64 + d;
                *(uint2*)&dst[o] = make_uint2(f2tf(acc[i][j][0] + bv0), f2tf(acc[i][j][1] + bv1));
            }
            {
                const int m = m0 + 8;
                size_t o = (((size_t)(m >> 6) * 8 + h) * 64 + (m & 63)) * 64 + d;
                *(uint2*)&dst[o] = make_uint2(f2tf(acc[i][j][2] + bv0), f2tf(acc[i][j][3] + bv1));
            }
        }
    }
}

// ---------------------------------------------------------------------------
// Kernel B: per-(window, head) attention. 4096 CTAs x 128 threads.
// Inputs are tf32 bits -> uint4 loads, no conversion.
// ---------------------------------------------------------------------------
__global__ void __launch_bounds__(128, 1) attn_kernel(
    const float* __restrict__ Bbias, float* __restrict__ out)
{
    extern __shared__ uint32_t smbuf[];
    uint32_t* qp_s = smbuf;               // [64][68] Q, later P (warp-private rows)
    uint32_t* k_s  = smbuf + 64 * 68;     // [t][d]
    uint32_t* v_s  = smbuf + 2 * 64 * 68; // [d][t]

    const int tid  = threadIdx.x;
    const int warp = tid >> 5, lane = tid & 31;
    const int g = lane >> 2, tig = lane & 3;
    const int wh = blockIdx.x;
    const int h  = wh & 7;
    const int bw = wh >> 3;
    const size_t base = (size_t)wh * 4096;

    const uint4* q4 = (const uint4*)(g_qkv + base);
    const uint4* k4 = (const uint4*)(g_qkv + QKV_SZ + base);
    const uint4* v4 = (const uint4*)(g_qkv + 2u * QKV_SZ + base);

#pragma unroll
    for (int i = 0; i < 8; i++) {
        const int c = i * 128 + tid;
        const int t = c >> 4, d4 = (c & 15) * 4;
        uint4 q = q4[c];
        uint4 k = k4[c];
        uint4 v = v4[c];
        *(uint4*)&qp_s[t * 68 + d4] = q;
        *(uint4*)&k_s [t * 68 + d4] = k;
        v_s[(d4    ) * 68 + t] = v.x;
        v_s[(d4 + 1) * 68 + t] = v.y;
        v_s[(d4 + 2) * 68 + t] = v.z;
        v_s[(d4 + 3) * 68 + t] = v.w;
    }
    __syncthreads();

    const int qr = warp * 16;

    float s[8][4];
#pragma unroll
    for (int j = 0; j < 8; j++)
#pragma unroll
        for (int c = 0; c < 4; c++) s[j][c] = 0.f;

#pragma unroll
    for (int k8 = 0; k8 < 8; k8++) {
        uint32_t a[4];
        a[0] = qp_s[(qr + g    ) * 68 + k8 * 8 + tig];
        a[1] = qp_s[(qr + g + 8) * 68 + k8 * 8 + tig];
        a[2] = qp_s[(qr + g    ) * 68 + k8 * 8 + tig + 4];
        a[3] = qp_s[(qr + g + 8) * 68 + k8 * 8 + tig + 4];
#pragma unroll
        for (int j = 0; j < 8; j++) {
            uint32_t b[2];
            b[0] = k_s[(j * 8 + g) * 68 + k8 * 8 + tig];
            b[1] = k_s[(j * 8 + g) * 68 + k8 * 8 + tig + 4];
            mma_tf32(s[j], a, b);
        }
    }

    const float scale = 0.125f;
    float mx0 = -1e30f, mx1 = -1e30f;
#pragma unroll
    for (int j = 0; j < 8; j++) {
        float2 b0 = *(const float2*)&Bbias[(qr + g    ) * 64 + j * 8 + tig * 2];
        float2 b1 = *(const float2*)&Bbias[(qr + g + 8) * 64 + j * 8 + tig * 2];
        s[j][0] = s[j][0] * scale + b0.x;
        s[j][1] = s[j][1] * scale + b0.y;
        s[j][2] = s[j][2] * scale + b1.x;
        s[j][3] = s[j][3] * scale + b1.y;
        mx0 = fmaxf(mx0, fmaxf(s[j][0], s[j][1]));
        mx1 = fmaxf(mx1, fmaxf(s[j][2], s[j][3]));
    }
    mx0 = fmaxf(mx0, __shfl_xor_sync(0xffffffffu, mx0, 1));
    mx0 = fmaxf(mx0, __shfl_xor_sync(0xffffffffu, mx0, 2));
    mx1 = fmaxf(mx1, __shfl_xor_sync(0xffffffffu, mx1, 1));
    mx1 = fmaxf(mx1, __shfl_xor_sync(0xffffffffu, mx1, 2));

    float sum0 = 0.f, sum1 = 0.f;
#pragma unroll
    for (int j = 0; j < 8; j++) {
        s[j][0] = __expf(s[j][0] - mx0);
        s[j][1] = __expf(s[j][1] - mx0);
        s[j][2] = __expf(s[j][2] - mx1);
        s[j][3] = __expf(s[j][3] - mx1);
        sum0 += s[j][0] + s[j][1];
        sum1 += s[j][2] + s[j][3];
    }
    sum0 += __shfl_xor_sync(0xffffffffu, sum0, 1);
    sum0 += __shfl_xor_sync(0xffffffffu, sum0, 2);
    sum1 += __shfl_xor_sync(0xffffffffu, sum1, 1);
    sum1 += __shfl_xor_sync(0xffffffffu, sum1, 2);
    const float inv0 = 1.0f / sum0, inv1 = 1.0f / sum1;

    __syncwarp();
#pragma unroll
    for (int j = 0; j < 8; j++) {
        qp_s[(qr + g    ) * 68 + j * 8 + tig * 2    ] = f2tf(s[j][0] * inv0);
        qp_s[(qr + g    ) * 68 + j * 8 + tig * 2 + 1] = f2tf(s[j][1] * inv0);
        qp_s[(qr + g + 8) * 68 + j * 8 + tig * 2    ] = f2tf(s[j][2] * inv1);
        qp_s[(qr + g + 8) * 68 + j * 8 + tig * 2 + 1] = f2tf(s[j][3] * inv1);
    }
    __syncwarp();

    float o[8][4];
#pragma unroll
    for (int j = 0; j < 8; j++)
#pragma unroll
        for (int c = 0; c < 4; c++) o[j][c] = 0.f;

#pragma unroll
    for (int k8 = 0; k8 < 8; k8++) {
        uint32_t a[4];
        a[0] = qp_s[(qr + g    ) * 68 + k8 * 8 + tig];
        a[1] = qp_s[(qr + g + 8) * 68 + k8 * 8 + tig];
        a[2] = qp_s[(qr + g    ) * 68 + k8 * 8 + tig + 4];
        a[3] = qp_s[(qr + g + 8) * 68 + k8 * 8 + tig + 4];
#pragma unroll
        for (int j = 0; j < 8; j++) {
            uint32_t b[2];
            b[0] = v_s[(j * 8 + g) * 68 + k8 * 8 + tig];
            b[1] = v_s[(j * 8 + g) * 68 + k8 * 8 + tig + 4];
            mma_tf32(o[j], a, b);
        }
    }

    float* o0 = out + ((size_t)bw * 64 + qr + g) * 512 + h * 64;
    float* o1 = o0 + 8 * 512;
#pragma unroll
    for (int j = 0; j < 8; j++) {
        *(float2*)&o0[j * 8 + tig * 2] = make_float2(o[j][0], o[j][1]);
        *(float2*)&o1[j * 8 + tig * 2] = make_float2(o[j][2], o[j][3]);
    }
}

// ---------------------------------------------------------------------------
extern "C" void kernel_launch(void* const* d_in, const int* in_sizes, int n_in,
                              void* d_out, int out_size)
{
    const float* x  = (const float*)d_in[0];
    const float* Wq = (const float*)d_in[1];
    const float* bq = (const float*)d_in[2];
    const float* Wk = (const float*)d_in[3];
    const float* bk = (const float*)d_in[4];
    const float* Wv = (const float*)d_in[5];
    const float* bv = (const float*)d_in[6];
    const float* Bb = (const float*)d_in[7];
    float* out = (float*)d_out;

    cudaFuncSetAttribute(qkv_proj_kernel, cudaFuncAttributeMaxDynamicSharedMemorySize,
                         PROJ_SMEM);
    cudaFuncSetAttribute(attn_kernel, cudaFuncAttributeMaxDynamicSharedMemorySize,
                         3 * 64 * 68 * 4);

    conv_x_kernel<<<16384, 256>>>(x);
    conv_w_kernel<<<768, 256>>>(Wq, Wk, Wv);

    dim3 gA(12, 128);   // x = N-tile (fast) -> x L2 reuse across N
    qkv_proj_kernel<<<gA, 256, PROJ_SMEM>>>(bq, bk, bv);

    attn_kernel<<<4096, 128, 3 * 64 * 68 * 4>>>(Bb, out);
}

// round 7
// speedup vs baseline: 2.4081x; 2.4081x over previous
#include <cuda_runtime.h>
#include <cuda_fp16.h>
#include <cstdint>

#define QKV_SZ (512u * 8u * 64u * 64u)   // halfs per matrix (16.78M)
// Scratch (device globals; no runtime allocation).
__device__ __align__(16) __half g_qkv[3 * QKV_SZ];   // fp16 [which][bw][h][t][d]
__device__ __align__(16) __half g_xh[32768u * 512u]; // x as fp16
__device__ __align__(16) __half g_wh[1536u * 512u];  // Wq|Wk|Wv as fp16

__device__ __forceinline__ uint32_t pack2(float a, float b) {
    __half2 h = __halves2half2(__float2half_rn(a), __float2half_rn(b));
    return *(uint32_t*)&h;
}

__device__ __forceinline__ void mma_f16(float c[4], const uint32_t a[4], const uint32_t b[2]) {
    asm volatile(
        "mma.sync.aligned.m16n8k16.row.col.f32.f16.f16.f32 "
        "{%0,%1,%2,%3}, {%4,%5,%6,%7}, {%8,%9}, {%0,%1,%2,%3};"
        : "+f"(c[0]), "+f"(c[1]), "+f"(c[2]), "+f"(c[3])
        : "r"(a[0]), "r"(a[1]), "r"(a[2]), "r"(a[3]), "r"(b[0]), "r"(b[1]));
}

__device__ __forceinline__ void cp_async16(uint32_t smem_addr, const void* gptr) {
    asm volatile("cp.async.cg.shared.global [%0], [%1], 16;\n" :: "r"(smem_addr), "l"(gptr));
}
__device__ __forceinline__ void cp_commit() { asm volatile("cp.async.commit_group;"); }
template <int N> __device__ __forceinline__ void cp_wait() {
    asm volatile("cp.async.wait_group %0;" :: "n"(N));
}

// ---------------------------------------------------------------------------
// Pre-convert: fp32 -> fp16(RN). 8 floats per thread.
// ---------------------------------------------------------------------------
__global__ void __launch_bounds__(256) conv_x_kernel(const float* __restrict__ x)
{
    const int i = blockIdx.x * 256 + threadIdx.x;   // 2,097,152 threads
    float4 v0 = ((const float4*)x)[2 * i];
    float4 v1 = ((const float4*)x)[2 * i + 1];
    uint4 u;
    u.x = pack2(v0.x, v0.y); u.y = pack2(v0.z, v0.w);
    u.z = pack2(v1.x, v1.y); u.w = pack2(v1.z, v1.w);
    ((uint4*)g_xh)[i] = u;
}

__global__ void __launch_bounds__(256) conv_w_kernel(
    const float* __restrict__ Wq, const float* __restrict__ Wk, const float* __restrict__ Wv)
{
    const int i = blockIdx.x * 256 + threadIdx.x;   // 98,304 threads (32768 per matrix)
    const int which = i >> 15;
    const int sub = i & 32767;
    const float* W = (which == 0) ? Wq : (which == 1) ? Wk : Wv;
    float4 v0 = ((const float4*)W)[2 * sub];
    float4 v1 = ((const float4*)W)[2 * sub + 1];
    uint4 u;
    u.x = pack2(v0.x, v0.y); u.y = pack2(v0.z, v0.w);
    u.z = pack2(v1.x, v1.y); u.w = pack2(v1.z, v1.w);
    ((uint4*)g_wh)[i] = u;
}

// ---------------------------------------------------------------------------
// Kernel A: QKV projection, fp16 mma m16n8k16, fp32 accumulate.
// y[m,n] = sum_k x[m,k]*W[n,k] + b[n].  M=32768, N=1536, K=512.
// CTA tile 256x128, 256 threads (8 warps, 64x64). K chunk 32 halfs (64B rows).
// 4-stage cp.async pipeline. Epilogue: +bias (fp32), fp16 scatter [bw][h][t][d].
// Grid (12, 128): blockIdx.x = N-tile (fast) -> x reused across N via L2.
// ---------------------------------------------------------------------------
#define KC 32
#define PW 20                            // words per staged row (16 data + 4 pad)
#define ROWS_STG 384                     // 256 A + 128 B
#define STAGE_W (ROWS_STG * PW)          // 7680 words
#define NSTAGE 4
#define PROJ_SMEM (NSTAGE * STAGE_W * 4) // 122880 B

__global__ void __launch_bounds__(256) qkv_proj_kernel(
    const float* __restrict__ bq, const float* __restrict__ bk, const float* __restrict__ bv)
{
    extern __shared__ uint32_t sm[];

    const int tid  = threadIdx.x;
    const int warp = tid >> 5, lane = tid & 31;
    const int g = lane >> 2, tig = lane & 3;
    const int wm = (warp >> 1) * 64;     // 4x2 warp grid of 64x64 tiles
    const int wn = (warp & 1) * 64;

    const int nb = blockIdx.x * 128;     // concatenated N
    const int mb = blockIdx.y * 256;
    const int which = nb >> 9;
    const int nw0 = nb & 511;
    const float* __restrict__ bias = (which == 0) ? bq : (which == 1) ? bk : bv;
    __half* __restrict__ dst = g_qkv + (size_t)which * QKV_SZ;

    const uint32_t smem_base = (uint32_t)__cvta_generic_to_shared(sm);

    float acc[4][8][4];
#pragma unroll
    for (int i = 0; i < 4; i++)
#pragma unroll
        for (int j = 0; j < 8; j++)
#pragma unroll
            for (int c = 0; c < 4; c++) acc[i][j][c] = 0.f;

    // Per stage: A 256 rows x 4 x 16B, B 128 rows x 4 x 16B = 1536 ops, 6/thread.
    auto issue = [&](int c) {
        const uint32_t sbase = smem_base + (uint32_t)((c & 3) * STAGE_W) * 4u;
        const int kel = c * KC;          // half offset in K
#pragma unroll
        for (int q = 0; q < 6; q++) {
            const int idx = q * 256 + tid;
            if (idx < 1024) {            // A
                const int row = idx >> 2, i = idx & 3;
                cp_async16(sbase + (uint32_t)(row * PW + i * 4) * 4u,
                           g_xh + (size_t)(mb + row) * 512 + kel + i * 8);
            } else {                     // B
                const int bidx = idx - 1024;
                const int row = bidx >> 2, i = bidx & 3;
                cp_async16(sbase + (uint32_t)((256 + row) * PW + i * 4) * 4u,
                           g_wh + (size_t)(nb + row) * 512 + kel + i * 8);
            }
        }
        cp_commit();
    };

    issue(0); issue(1); issue(2);

    for (int c = 0; c < 16; c++) {
        if (c <= 13) cp_wait<2>();
        else if (c == 14) cp_wait<1>();
        else cp_wait<0>();
        __syncthreads();
        if (c + 3 < 16) issue(c + 3);

        const uint32_t* A = sm + (c & 3) * STAGE_W;
        const uint32_t* B = A + 256 * PW;

#pragma unroll
        for (int step = 0; step < 2; step++) {   // two k16 per 32-chunk
            uint32_t a[4][4];
#pragma unroll
            for (int i = 0; i < 4; i++) {
                const int r0 = (wm + i * 16 + g) * PW + step * 8 + tig;
                a[i][0] = A[r0];
                a[i][1] = A[r0 + 8 * PW];
                a[i][2] = A[r0 + 4];
                a[i][3] = A[r0 + 8 * PW + 4];
            }
#pragma unroll
            for (int j = 0; j < 8; j++) {
                const int rb = (wn + j * 8 + g) * PW + step * 8 + tig;
                uint32_t b[2];
                b[0] = B[rb];
                b[1] = B[rb + 4];
#pragma unroll
                for (int i = 0; i < 4; i++) mma_f16(acc[i][j], a[i], b);
            }
        }
    }

    // Epilogue: +bias in fp32, pack half2, scatter [bw][h][t][d].
#pragma unroll
    for (int i = 0; i < 4; i++) {
        const int m0 = mb + wm + i * 16 + g;
#pragma unroll
        for (int j = 0; j < 8; j++) {
            const int col = nw0 + wn + j * 8 + tig * 2;   // within matrix
            const float bv0 = bias[col], bv1 = bias[col + 1];
            const int h = col >> 6, d = col & 63;
            {
                const int m = m0;
                size_t o = (((size_t)(m >> 6) * 8 + h) * 64 + (m & 63)) * 64 + d;
                *(uint32_t*)&dst[o] = pack2(acc[i][j][0] + bv0, acc[i][j][1] + bv1);
            }
            {
                const int m = m0 + 8;
                size_t o = (((size_t)(m >> 6) * 8 + h) * 64 + (m & 63)) * 64 + d;
                *(uint32_t*)&dst[o] = pack2(acc[i][j][2] + bv0, acc[i][j][3] + bv1);
            }
        }
    }
}

// ---------------------------------------------------------------------------
// Kernel B: per-(window, head) attention, fp16 mma. 4096 CTAs x 128 threads.
// Q,K,V fp16 [t][d] (pitch 72 halfs = 36 words). V's B-operand loaded with
// ldmatrix.x2.trans (no transposed stores). S/softmax in fp32; P fp16.
// ---------------------------------------------------------------------------
#define APITCH 36   // words per 64-half row (72 halfs)

__global__ void __launch_bounds__(128) attn_kernel(
    const float* __restrict__ Bbias, float* __restrict__ out)
{
    __shared__ uint32_t qp_s[64 * APITCH];   // Q, later P (warp-private rows)
    __shared__ uint32_t k_s [64 * APITCH];
    __shared__ uint32_t v_s [64 * APITCH];   // [t][d] row-major

    const int tid  = threadIdx.x;
    const int warp = tid >> 5, lane = tid & 31;
    const int g = lane >> 2, tig = lane & 3;
    const int wh = blockIdx.x;
    const int h  = wh & 7;
    const int bw = wh >> 3;
    const size_t base = (size_t)wh * 4096;   // halfs

    const uint4* q4 = (const uint4*)(g_qkv + base);
    const uint4* k4 = (const uint4*)(g_qkv + QKV_SZ + base);
    const uint4* v4 = (const uint4*)(g_qkv + 2u * QKV_SZ + base);

#pragma unroll
    for (int i = 0; i < 4; i++) {
        const int c = i * 128 + tid;         // 0..511 uint4 (8 halfs each)
        const int t = c >> 3, w4 = (c & 7) * 4;
        *(uint4*)&qp_s[t * APITCH + w4] = q4[c];
        *(uint4*)&k_s [t * APITCH + w4] = k4[c];
        *(uint4*)&v_s [t * APITCH + w4] = v4[c];
    }
    __syncthreads();

    const int qr = warp * 16;

    // ---- S = Q K^T (k = d, 4 x k16) ----
    float s[8][4];
#pragma unroll
    for (int j = 0; j < 8; j++)
#pragma unroll
        for (int c = 0; c < 4; c++) s[j][c] = 0.f;

#pragma unroll
    for (int kk = 0; kk < 4; kk++) {
        uint32_t a[4];
        const int r0 = (qr + g) * APITCH + kk * 8 + tig;
        a[0] = qp_s[r0];
        a[1] = qp_s[r0 + 8 * APITCH];
        a[2] = qp_s[r0 + 4];
        a[3] = qp_s[r0 + 8 * APITCH + 4];
#pragma unroll
        for (int j = 0; j < 8; j++) {
            const int rb = (j * 8 + g) * APITCH + kk * 8 + tig;
            uint32_t b[2];
            b[0] = k_s[rb];
            b[1] = k_s[rb + 4];
            mma_f16(s[j], a, b);
        }
    }

    // ---- scale + bias + softmax (rows qr+g, qr+g+8; quad owns a row) ----
    const float scale = 0.125f;
    float mx0 = -1e30f, mx1 = -1e30f;
#pragma unroll
    for (int j = 0; j < 8; j++) {
        float2 b0 = *(const float2*)&Bbias[(qr + g    ) * 64 + j * 8 + tig * 2];
        float2 b1 = *(const float2*)&Bbias[(qr + g + 8) * 64 + j * 8 + tig * 2];
        s[j][0] = s[j][0] * scale + b0.x;
        s[j][1] = s[j][1] * scale + b0.y;
        s[j][2] = s[j][2] * scale + b1.x;
        s[j][3] = s[j][3] * scale + b1.y;
        mx0 = fmaxf(mx0, fmaxf(s[j][0], s[j][1]));
        mx1 = fmaxf(mx1, fmaxf(s[j][2], s[j][3]));
    }
    mx0 = fmaxf(mx0, __shfl_xor_sync(0xffffffffu, mx0, 1));
    mx0 = fmaxf(mx0, __shfl_xor_sync(0xffffffffu, mx0, 2));
    mx1 = fmaxf(mx1, __shfl_xor_sync(0xffffffffu, mx1, 1));
    mx1 = fmaxf(mx1, __shfl_xor_sync(0xffffffffu, mx1, 2));

    float sum0 = 0.f, sum1 = 0.f;
#pragma unroll
    for (int j = 0; j < 8; j++) {
        s[j][0] = __expf(s[j][0] - mx0);
        s[j][1] = __expf(s[j][1] - mx0);
        s[j][2] = __expf(s[j][2] - mx1);
        s[j][3] = __expf(s[j][3] - mx1);
        sum0 += s[j][0] + s[j][1];
        sum1 += s[j][2] + s[j][3];
    }
    sum0 += __shfl_xor_sync(0xffffffffu, sum0, 1);
    sum0 += __shfl_xor_sync(0xffffffffu, sum0, 2);
    sum1 += __shfl_xor_sync(0xffffffffu, sum1, 1);
    sum1 += __shfl_xor_sync(0xffffffffu, sum1, 2);
    const float inv0 = 1.0f / sum0, inv1 = 1.0f / sum1;

    // ---- P (fp16) over Q smem: row qr+g cols j*8+2tig -> word j*4+tig ----
    __syncwarp();
#pragma unroll
    for (int j = 0; j < 8; j++) {
        qp_s[(qr + g    ) * APITCH + j * 4 + tig] = pack2(s[j][0] * inv0, s[j][1] * inv0);
        qp_s[(qr + g + 8) * APITCH + j * 4 + tig] = pack2(s[j][2] * inv1, s[j][3] * inv1);
    }
    __syncwarp();

    // ---- O = P V (k = token, 4 x k16; B via ldmatrix.trans from V[t][d]) ----
    float o[8][4];
#pragma unroll
    for (int j = 0; j < 8; j++)
#pragma unroll
        for (int c = 0; c < 4; c++) o[j][c] = 0.f;

#pragma unroll
    for (int kk = 0; kk < 4; kk++) {
        uint32_t a[4];
        const int r0 = (qr + g) * APITCH + kk * 8 + tig;
        a[0] = qp_s[r0];
        a[1] = qp_s[r0 + 8 * APITCH];
        a[2] = qp_s[r0 + 4];
        a[3] = qp_s[r0 + 8 * APITCH + 4];
        // lane row for ldmatrix: k-rows kk*16 + (lane&15)
        const uint32_t vrow_addr =
            (uint32_t)__cvta_generic_to_shared(&v_s[(kk * 16 + (lane & 15)) * APITCH]);
#pragma unroll
        for (int j = 0; j < 8; j++) {
            uint32_t b0, b1;
            asm volatile(
                "ldmatrix.sync.aligned.m8n8.x2.trans.shared.b16 {%0,%1}, [%2];"
                : "=r"(b0), "=r"(b1) : "r"(vrow_addr + (uint32_t)(j * 16)));
            uint32_t b[2] = {b0, b1};
            mma_f16(o[j], a, b);
        }
    }

    // ---- output: flat[((bw*64 + t) * 512) + h*64 + d], fp32 ----
    float* o0 = out + ((size_t)bw * 64 + qr + g) * 512 + h * 64;
    float* o1 = o0 + 8 * 512;
#pragma unroll
    for (int j = 0; j < 8; j++) {
        *(float2*)&o0[j * 8 + tig * 2] = make_float2(o[j][0], o[j][1]);
        *(float2*)&o1[j * 8 + tig * 2] = make_float2(o[j][2], o[j][3]);
    }
}

// ---------------------------------------------------------------------------
extern "C" void kernel_launch(void* const* d_in, const int* in_sizes, int n_in,
                              void* d_out, int out_size)
{
    const float* x  = (const float*)d_in[0];
    const float* Wq = (const float*)d_in[1];
    const float* bq = (const float*)d_in[2];
    const float* Wk = (const float*)d_in[3];
    const float* bk = (const float*)d_in[4];
    const float* Wv = (const float*)d_in[5];
    const float* bv = (const float*)d_in[6];
    const float* Bb = (const float*)d_in[7];
    float* out = (float*)d_out;

    cudaFuncSetAttribute(qkv_proj_kernel, cudaFuncAttributeMaxDynamicSharedMemorySize,
                         PROJ_SMEM);

    conv_x_kernel<<<8192, 256>>>(x);
    conv_w_kernel<<<384, 256>>>(Wq, Wk, Wv);

    dim3 gA(12, 128);   // x = N-tile (fast) -> x L2 reuse across N
    qkv_proj_kernel<<<gA, 256, PROJ_SMEM>>>(bq, bk, bv);

    attn_kernel<<<4096, 128>>>(Bb, out);
}

// round 8
// speedup vs baseline: 2.4689x; 1.0252x over previous
#include <cuda_runtime.h>
#include <cuda_fp16.h>
#include <cstdint>

#define QKV_SZ (512u * 8u * 64u * 64u)   // halfs per matrix
__device__ __align__(16) __half g_qkv[3 * QKV_SZ];   // fp16 [which][bw][h][t][d]
__device__ __align__(16) __half g_xh[32768u * 512u]; // x as fp16
__device__ __align__(16) __half g_wh[1536u * 512u];  // Wq|Wk|Wv as fp16

__device__ __forceinline__ uint32_t pack2(float a, float b) {
    __half2 h = __halves2half2(__float2half_rn(a), __float2half_rn(b));
    return *(uint32_t*)&h;
}

__device__ __forceinline__ void mma_f16(float c[4], const uint32_t a[4],
                                        uint32_t b0, uint32_t b1) {
    asm volatile(
        "mma.sync.aligned.m16n8k16.row.col.f32.f16.f16.f32 "
        "{%0,%1,%2,%3}, {%4,%5,%6,%7}, {%8,%9}, {%0,%1,%2,%3};"
        : "+f"(c[0]), "+f"(c[1]), "+f"(c[2]), "+f"(c[3])
        : "r"(a[0]), "r"(a[1]), "r"(a[2]), "r"(a[3]), "r"(b0), "r"(b1));
}

__device__ __forceinline__ void ldm_x4(uint32_t* r, uint32_t addr) {
    asm volatile("ldmatrix.sync.aligned.m8n8.x4.shared.b16 {%0,%1,%2,%3}, [%4];"
                 : "=r"(r[0]), "=r"(r[1]), "=r"(r[2]), "=r"(r[3]) : "r"(addr));
}
__device__ __forceinline__ void ldm_x4_trans(uint32_t* r, uint32_t addr) {
    asm volatile("ldmatrix.sync.aligned.m8n8.x4.trans.shared.b16 {%0,%1,%2,%3}, [%4];"
                 : "=r"(r[0]), "=r"(r[1]), "=r"(r[2]), "=r"(r[3]) : "r"(addr));
}

__device__ __forceinline__ void cp_async16(uint32_t smem_addr, const void* gptr) {
    asm volatile("cp.async.cg.shared.global [%0], [%1], 16;\n" :: "r"(smem_addr), "l"(gptr));
}
__device__ __forceinline__ void cp_commit() { asm volatile("cp.async.commit_group;"); }
template <int N> __device__ __forceinline__ void cp_wait() {
    asm volatile("cp.async.wait_group %0;" :: "n"(N));
}

// ---------------------------------------------------------------------------
// Pre-convert: fp32 -> fp16(RN). 8 floats per thread.
// ---------------------------------------------------------------------------
__global__ void __launch_bounds__(256) conv_x_kernel(const float* __restrict__ x)
{
    const int i = blockIdx.x * 256 + threadIdx.x;
    float4 v0 = ((const float4*)x)[2 * i];
    float4 v1 = ((const float4*)x)[2 * i + 1];
    uint4 u;
    u.x = pack2(v0.x, v0.y); u.y = pack2(v0.z, v0.w);
    u.z = pack2(v1.x, v1.y); u.w = pack2(v1.z, v1.w);
    ((uint4*)g_xh)[i] = u;
}

__global__ void __launch_bounds__(256) conv_w_kernel(
    const float* __restrict__ Wq, const float* __restrict__ Wk, const float* __restrict__ Wv)
{
    const int i = blockIdx.x * 256 + threadIdx.x;
    const int which = i >> 15;
    const int sub = i & 32767;
    const float* W = (which == 0) ? Wq : (which == 1) ? Wk : Wv;
    float4 v0 = ((const float4*)W)[2 * sub];
    float4 v1 = ((const float4*)W)[2 * sub + 1];
    uint4 u;
    u.x = pack2(v0.x, v0.y); u.y = pack2(v0.z, v0.w);
    u.z = pack2(v1.x, v1.y); u.w = pack2(v1.z, v1.w);
    ((uint4*)g_wh)[i] = u;
}

// ---------------------------------------------------------------------------
// Kernel A: QKV projection, fp16 m16n8k16, ldmatrix.x4 operand delivery.
// CTA 256x128, 256 threads, 8 warps (64x64 tiles). K chunk 32, 4-stage cp.async.
// Grid (12, 128): blockIdx.x = N-tile (fast) -> x L2 reuse.
// ---------------------------------------------------------------------------
#define KC 32
#define PW 20                            // words per staged row (16 data + 4 pad)
#define STAGE_W (384 * PW)               // 256 A rows + 128 B rows
#define NSTAGE 4
#define PROJ_SMEM (NSTAGE * STAGE_W * 4) // 122880 B

__global__ void __launch_bounds__(256) qkv_proj_kernel(
    const float* __restrict__ bq, const float* __restrict__ bk, const float* __restrict__ bv)
{
    extern __shared__ uint32_t sm[];

    const int tid  = threadIdx.x;
    const int warp = tid >> 5, lane = tid & 31;
    const int g = lane >> 2, tig = lane & 3;
    const int l8 = lane >> 3, r8 = lane & 7;
    const int wm = (warp >> 1) * 64;
    const int wn = (warp & 1) * 64;

    const int nb = blockIdx.x * 128;
    const int mb = blockIdx.y * 256;
    const int which = nb >> 9;
    const int nw0 = nb & 511;
    const float* __restrict__ bias = (which == 0) ? bq : (which == 1) ? bk : bv;
    __half* __restrict__ dst = g_qkv + (size_t)which * QKV_SZ;

    const uint32_t smem_base = (uint32_t)__cvta_generic_to_shared(sm);

    // Per-lane ldmatrix word offsets (within a stage).
    // A fragment i: submats (rows0-7,k0)(rows8-15,k0)(rows0-7,k8)(rows8-15,k8)
    const uint32_t a_off = (uint32_t)((wm + (l8 & 1) * 8 + r8) * PW + (l8 >> 1) * 4);
    // B fragment jj: submats (j,k0)(j,k8)(j+1,k0)(j+1,k8), rows at 256+
    const uint32_t b_off = (uint32_t)((256 + wn + (l8 >> 1) * 8 + r8) * PW + (l8 & 1) * 4);

    float acc[4][8][4];
#pragma unroll
    for (int i = 0; i < 4; i++)
#pragma unroll
        for (int j = 0; j < 8; j++)
#pragma unroll
            for (int c = 0; c < 4; c++) acc[i][j][c] = 0.f;

    auto issue = [&](int c) {
        const uint32_t sbase = smem_base + (uint32_t)((c & 3) * STAGE_W) * 4u;
        const int kel = c * KC;
#pragma unroll
        for (int q = 0; q < 6; q++) {
            const int idx = q * 256 + tid;
            if (idx < 1024) {
                const int row = idx >> 2, i = idx & 3;
                cp_async16(sbase + (uint32_t)(row * PW + i * 4) * 4u,
                           g_xh + (size_t)(mb + row) * 512 + kel + i * 8);
            } else {
                const int bidx = idx - 1024;
                const int row = bidx >> 2, i = bidx & 3;
                cp_async16(sbase + (uint32_t)((256 + row) * PW + i * 4) * 4u,
                           g_wh + (size_t)(nb + row) * 512 + kel + i * 8);
            }
        }
        cp_commit();
    };

    issue(0); issue(1); issue(2);

    for (int c = 0; c < 16; c++) {
        if (c <= 13) cp_wait<2>();
        else if (c == 14) cp_wait<1>();
        else cp_wait<0>();
        __syncthreads();
        if (c + 3 < 16) issue(c + 3);

        const uint32_t stage_addr = smem_base + (uint32_t)((c & 3) * STAGE_W) * 4u;

#pragma unroll
        for (int step = 0; step < 2; step++) {
            const uint32_t so = stage_addr + (uint32_t)(step * 8) * 4u;
            uint32_t a[4][4];
#pragma unroll
            for (int i = 0; i < 4; i++)
                ldm_x4(a[i], so + (a_off + (uint32_t)(i * 16 * PW)) * 4u);
#pragma unroll
            for (int jj = 0; jj < 4; jj++) {
                uint32_t b[4];
                ldm_x4(b, so + (b_off + (uint32_t)(jj * 16 * PW)) * 4u);
#pragma unroll
                for (int i = 0; i < 4; i++) {
                    mma_f16(acc[i][2 * jj    ], a[i], b[0], b[1]);
                    mma_f16(acc[i][2 * jj + 1], a[i], b[2], b[3]);
                }
            }
        }
    }

    // Epilogue: +bias fp32, pack half2, scatter [bw][h][t][d].
#pragma unroll
    for (int i = 0; i < 4; i++) {
        const int m0 = mb + wm + i * 16 + g;
#pragma unroll
        for (int j = 0; j < 8; j++) {
            const int col = nw0 + wn + j * 8 + tig * 2;
            const float bv0 = bias[col], bv1 = bias[col + 1];
            const int h = col >> 6, d = col & 63;
            {
                const int m = m0;
                size_t o = (((size_t)(m >> 6) * 8 + h) * 64 + (m & 63)) * 64 + d;
                *(uint32_t*)&dst[o] = pack2(acc[i][j][0] + bv0, acc[i][j][1] + bv1);
            }
            {
                const int m = m0 + 8;
                size_t o = (((size_t)(m >> 6) * 8 + h) * 64 + (m & 63)) * 64 + d;
                *(uint32_t*)&dst[o] = pack2(acc[i][j][2] + bv0, acc[i][j][3] + bv1);
            }
        }
    }
}

// ---------------------------------------------------------------------------
// Kernel B: per-(window, head) attention, fp16 mma + ldmatrix.x4.
// 4096 CTAs x 128 threads. Q/K/V fp16 [t][d], pitch 36 words.
// ---------------------------------------------------------------------------
#define APITCH 36

__global__ void __launch_bounds__(128) attn_kernel(
    const float* __restrict__ Bbias, float* __restrict__ out)
{
    __shared__ uint32_t qp_s[64 * APITCH];   // Q, later P (warp-private rows)
    __shared__ uint32_t k_s [64 * APITCH];
    __shared__ uint32_t v_s [64 * APITCH];   // [t][d] row-major

    const int tid  = threadIdx.x;
    const int warp = tid >> 5, lane = tid & 31;
    const int g = lane >> 2, tig = lane & 3;
    const int l8 = lane >> 3, r8 = lane & 7;
    const int wh = blockIdx.x;
    const int h  = wh & 7;
    const int bw = wh >> 3;
    const size_t base = (size_t)wh * 4096;

    const uint4* q4 = (const uint4*)(g_qkv + base);
    const uint4* k4 = (const uint4*)(g_qkv + QKV_SZ + base);
    const uint4* v4 = (const uint4*)(g_qkv + 2u * QKV_SZ + base);

#pragma unroll
    for (int i = 0; i < 4; i++) {
        const int c = i * 128 + tid;
        const int t = c >> 3, w4 = (c & 7) * 4;
        *(uint4*)&qp_s[t * APITCH + w4] = q4[c];
        *(uint4*)&k_s [t * APITCH + w4] = k4[c];
        *(uint4*)&v_s [t * APITCH + w4] = v4[c];
    }
    __syncthreads();

    const int qr = warp * 16;
    const uint32_t qp_base = (uint32_t)__cvta_generic_to_shared(qp_s);
    const uint32_t k_base  = (uint32_t)__cvta_generic_to_shared(k_s);
    const uint32_t v_base  = (uint32_t)__cvta_generic_to_shared(v_s);

    // Per-lane ldmatrix offsets (words)
    const uint32_t aq_off = (uint32_t)((qr + (l8 & 1) * 8 + r8) * APITCH + (l8 >> 1) * 4);
    const uint32_t bk_off = (uint32_t)(((l8 >> 1) * 8 + r8) * APITCH + (l8 & 1) * 4);
    // V trans: submats (t0-7,j)(t8-15,j)(t0-7,j+1)(t8-15,j+1)
    const uint32_t bv_off = (uint32_t)(((l8 & 1) * 8 + r8) * APITCH + (l8 >> 1) * 4);

    // ---- S = Q K^T ----
    float s[8][4];
#pragma unroll
    for (int j = 0; j < 8; j++)
#pragma unroll
        for (int c = 0; c < 4; c++) s[j][c] = 0.f;

#pragma unroll
    for (int kk = 0; kk < 4; kk++) {
        uint32_t a[4];
        ldm_x4(a, qp_base + (aq_off + (uint32_t)(kk * 8)) * 4u);
#pragma unroll
        for (int jj = 0; jj < 4; jj++) {
            uint32_t b[4];
            ldm_x4(b, k_base + (bk_off + (uint32_t)(jj * 16 * APITCH + kk * 8)) * 4u);
            mma_f16(s[2 * jj    ], a, b[0], b[1]);
            mma_f16(s[2 * jj + 1], a, b[2], b[3]);
        }
    }

    // ---- scale + bias + softmax ----
    const float scale = 0.125f;
    float mx0 = -1e30f, mx1 = -1e30f;
#pragma unroll
    for (int j = 0; j < 8; j++) {
        float2 b0 = *(const float2*)&Bbias[(qr + g    ) * 64 + j * 8 + tig * 2];
        float2 b1 = *(const float2*)&Bbias[(qr + g + 8) * 64 + j * 8 + tig * 2];
        s[j][0] = s[j][0] * scale + b0.x;
        s[j][1] = s[j][1] * scale + b0.y;
        s[j][2] = s[j][2] * scale + b1.x;
        s[j][3] = s[j][3] * scale + b1.y;
        mx0 = fmaxf(mx0, fmaxf(s[j][0], s[j][1]));
        mx1 = fmaxf(mx1, fmaxf(s[j][2], s[j][3]));
    }
    mx0 = fmaxf(mx0, __shfl_xor_sync(0xffffffffu, mx0, 1));
    mx0 = fmaxf(mx0, __shfl_xor_sync(0xffffffffu, mx0, 2));
    mx1 = fmaxf(mx1, __shfl_xor_sync(0xffffffffu, mx1, 1));
    mx1 = fmaxf(mx1, __shfl_xor_sync(0xffffffffu, mx1, 2));

    float sum0 = 0.f, sum1 = 0.f;
#pragma unroll
    for (int j = 0; j < 8; j++) {
        s[j][0] = __expf(s[j][0] - mx0);
        s[j][1] = __expf(s[j][1] - mx0);
        s[j][2] = __expf(s[j][2] - mx1);
        s[j][3] = __expf(s[j][3] - mx1);
        sum0 += s[j][0] + s[j][1];
        sum1 += s[j][2] + s[j][3];
    }
    sum0 += __shfl_xor_sync(0xffffffffu, sum0, 1);
    sum0 += __shfl_xor_sync(0xffffffffu, sum0, 2);
    sum1 += __shfl_xor_sync(0xffffffffu, sum1, 1);
    sum1 += __shfl_xor_sync(0xffffffffu, sum1, 2);
    const float inv0 = 1.0f / sum0, inv1 = 1.0f / sum1;

    // ---- P (fp16) over Q smem ----
    __syncwarp();
#pragma unroll
    for (int j = 0; j < 8; j++) {
        qp_s[(qr + g    ) * APITCH + j * 4 + tig] = pack2(s[j][0] * inv0, s[j][1] * inv0);
        qp_s[(qr + g + 8) * APITCH + j * 4 + tig] = pack2(s[j][2] * inv1, s[j][3] * inv1);
    }
    __syncwarp();

    // ---- O = P V ----
    float o[8][4];
#pragma unroll
    for (int j = 0; j < 8; j++)
#pragma unroll
        for (int c = 0; c < 4; c++) o[j][c] = 0.f;

#pragma unroll
    for (int kk = 0; kk < 4; kk++) {
        uint32_t a[4];
        ldm_x4(a, qp_base + (aq_off + (uint32_t)(kk * 8)) * 4u);
#pragma unroll
        for (int jj = 0; jj < 4; jj++) {
            uint32_t b[4];
            ldm_x4_trans(b, v_base + (bv_off + (uint32_t)(kk * 16 * APITCH + jj * 8)) * 4u);
            mma_f16(o[2 * jj    ], a, b[0], b[1]);
            mma_f16(o[2 * jj + 1], a, b[2], b[3]);
        }
    }

    // ---- output ----
    float* o0 = out + ((size_t)bw * 64 + qr + g) * 512 + h * 64;
    float* o1 = o0 + 8 * 512;
#pragma unroll
    for (int j = 0; j < 8; j++) {
        *(float2*)&o0[j * 8 + tig * 2] = make_float2(o[j][0], o[j][1]);
        *(float2*)&o1[j * 8 + tig * 2] = make_float2(o[j][2], o[j][3]);
    }
}

// ---------------------------------------------------------------------------
extern "C" void kernel_launch(void* const* d_in, const int* in_sizes, int n_in,
                              void* d_out, int out_size)
{
    const float* x  = (const float*)d_in[0];
    const float* Wq = (const float*)d_in[1];
    const float* bq = (const float*)d_in[2];
    const float* Wk = (const float*)d_in[3];
    const float* bk = (const float*)d_in[4];
    const float* Wv = (const float*)d_in[5];
    const float* bv = (const float*)d_in[6];
    const float* Bb = (const float*)d_in[7];
    float* out = (float*)d_out;

    cudaFuncSetAttribute(qkv_proj_kernel, cudaFuncAttributeMaxDynamicSharedMemorySize,
                         PROJ_SMEM);

    conv_x_kernel<<<8192, 256>>>(x);
    conv_w_kernel<<<384, 256>>>(Wq, Wk, Wv);

    dim3 gA(12, 128);
    qkv_proj_kernel<<<gA, 256, PROJ_SMEM>>>(bq, bk, bv);

    attn_kernel<<<4096, 128>>>(Bb, out);
}

// round 9
// speedup vs baseline: 2.7053x; 1.0958x over previous
#include <cuda_runtime.h>
#include <cuda_fp16.h>
#include <cstdint>

#define QKV_SZ (512u * 8u * 64u * 64u)   // halfs per matrix
__device__ __align__(16) __half g_qkv[3 * QKV_SZ];   // fp16 [which][bw][h][t][d]
__device__ __align__(16) __half g_xh[32768u * 512u]; // x as fp16
__device__ __align__(16) __half g_wh[1536u * 512u];  // Wq|Wk|Wv as fp16

__device__ __forceinline__ uint32_t pack2(float a, float b) {
    __half2 h = __halves2half2(__float2half_rn(a), __float2half_rn(b));
    return *(uint32_t*)&h;
}

__device__ __forceinline__ void mma_f16(float c[4], const uint32_t a[4],
                                        uint32_t b0, uint32_t b1) {
    asm volatile(
        "mma.sync.aligned.m16n8k16.row.col.f32.f16.f16.f32 "
        "{%0,%1,%2,%3}, {%4,%5,%6,%7}, {%8,%9}, {%0,%1,%2,%3};"
        : "+f"(c[0]), "+f"(c[1]), "+f"(c[2]), "+f"(c[3])
        : "r"(a[0]), "r"(a[1]), "r"(a[2]), "r"(a[3]), "r"(b0), "r"(b1));
}

__device__ __forceinline__ void ldm_x4(uint32_t* r, uint32_t addr) {
    asm volatile("ldmatrix.sync.aligned.m8n8.x4.shared.b16 {%0,%1,%2,%3}, [%4];"
                 : "=r"(r[0]), "=r"(r[1]), "=r"(r[2]), "=r"(r[3]) : "r"(addr));
}
__device__ __forceinline__ void ldm_x4_trans(uint32_t* r, uint32_t addr) {
    asm volatile("ldmatrix.sync.aligned.m8n8.x4.trans.shared.b16 {%0,%1,%2,%3}, [%4];"
                 : "=r"(r[0]), "=r"(r[1]), "=r"(r[2]), "=r"(r[3]) : "r"(addr));
}

__device__ __forceinline__ void cp_async16(uint32_t smem_addr, const void* gptr) {
    asm volatile("cp.async.cg.shared.global [%0], [%1], 16;\n" :: "r"(smem_addr), "l"(gptr));
}
__device__ __forceinline__ void cp_commit() { asm volatile("cp.async.commit_group;"); }
template <int N> __device__ __forceinline__ void cp_wait() {
    asm volatile("cp.async.wait_group %0;" :: "n"(N));
}

// ---------------------------------------------------------------------------
// Pre-convert: fp32 -> fp16(RN). 8 floats per thread.
// ---------------------------------------------------------------------------
__global__ void __launch_bounds__(256) conv_x_kernel(const float* __restrict__ x)
{
    const int i = blockIdx.x * 256 + threadIdx.x;
    float4 v0 = ((const float4*)x)[2 * i];
    float4 v1 = ((const float4*)x)[2 * i + 1];
    uint4 u;
    u.x = pack2(v0.x, v0.y); u.y = pack2(v0.z, v0.w);
    u.z = pack2(v1.x, v1.y); u.w = pack2(v1.z, v1.w);
    ((uint4*)g_xh)[i] = u;
}

__global__ void __launch_bounds__(256) conv_w_kernel(
    const float* __restrict__ Wq, const float* __restrict__ Wk, const float* __restrict__ Wv)
{
    const int i = blockIdx.x * 256 + threadIdx.x;
    const int which = i >> 15;
    const int sub = i & 32767;
    const float* W = (which == 0) ? Wq : (which == 1) ? Wk : Wv;
    float4 v0 = ((const float4*)W)[2 * sub];
    float4 v1 = ((const float4*)W)[2 * sub + 1];
    uint4 u;
    u.x = pack2(v0.x, v0.y); u.y = pack2(v0.z, v0.w);
    u.z = pack2(v1.x, v1.y); u.w = pack2(v1.z, v1.w);
    ((uint4*)g_wh)[i] = u;
}

// ---------------------------------------------------------------------------
// Kernel A: QKV projection, fp16 m16n8k16, 2 CTAs/SM.
// CTA tile 128x128, 256 threads, 8 warps (2x4 grid of 64x32 warp tiles).
// K chunk 32, 4-stage cp.async pipeline. ldmatrix.x4 operand delivery.
// Grid (12, 256): blockIdx.x = N-tile (fast) -> x L2 reuse.
// ---------------------------------------------------------------------------
#define KC 32
#define PW 20                            // words per staged row (16 data + 4 pad)
#define STAGE_W (256 * PW)               // 128 A rows + 128 B rows = 5120 words
#define NSTAGE 4
#define PROJ_SMEM (NSTAGE * STAGE_W * 4) // 81920 B -> 2 CTAs/SM

__global__ void __launch_bounds__(256, 2) qkv_proj_kernel(
    const float* __restrict__ bq, const float* __restrict__ bk, const float* __restrict__ bv)
{
    extern __shared__ uint32_t sm[];

    const int tid  = threadIdx.x;
    const int warp = tid >> 5, lane = tid & 31;
    const int g = lane >> 2, tig = lane & 3;
    const int l8 = lane >> 3, r8 = lane & 7;
    const int wm = (warp >> 2) * 64;     // 2 row-groups
    const int wn = (warp & 3) * 32;      // 4 col-groups

    const int nb = blockIdx.x * 128;
    const int mb = blockIdx.y * 128;
    const int which = nb >> 9;
    const int nw0 = nb & 511;
    const float* __restrict__ bias = (which == 0) ? bq : (which == 1) ? bk : bv;
    __half* __restrict__ dst = g_qkv + (size_t)which * QKV_SZ;

    const uint32_t smem_base = (uint32_t)__cvta_generic_to_shared(sm);

    // ldmatrix lane offsets (words, within stage).
    // A frag i: (rows wm+i*16 + {0-7,8-15}, k{0,8})
    const uint32_t a_off = (uint32_t)((wm + (l8 & 1) * 8 + r8) * PW + (l8 >> 1) * 4);
    // B frag jj: rows 128 + wn + jj*16 + n-octet; (n0-7,k0)(n0-7,k8)(n8-15,k0)(n8-15,k8)
    const uint32_t b_off = (uint32_t)((128 + wn + (l8 >> 1) * 8 + r8) * PW + (l8 & 1) * 4);

    float acc[4][4][4];
#pragma unroll
    for (int i = 0; i < 4; i++)
#pragma unroll
        for (int j = 0; j < 4; j++)
#pragma unroll
            for (int c = 0; c < 4; c++) acc[i][j][c] = 0.f;

    // Per stage: A 128 rows x 4 x 16B + B 128 rows x 4 x 16B = 1024 ops, 4/thread.
    auto issue = [&](int c) {
        const uint32_t sbase = smem_base + (uint32_t)((c & 3) * STAGE_W) * 4u;
        const int kel = c * KC;
#pragma unroll
        for (int q = 0; q < 4; q++) {
            const int idx = q * 256 + tid;
            if (idx < 512) {             // A
                const int row = idx >> 2, i = idx & 3;
                cp_async16(sbase + (uint32_t)(row * PW + i * 4) * 4u,
                           g_xh + (size_t)(mb + row) * 512 + kel + i * 8);
            } else {                     // B
                const int bidx = idx - 512;
                const int row = bidx >> 2, i = bidx & 3;
                cp_async16(sbase + (uint32_t)((128 + row) * PW + i * 4) * 4u,
                           g_wh + (size_t)(nb + row) * 512 + kel + i * 8);
            }
        }
        cp_commit();
    };

    issue(0); issue(1); issue(2);

    for (int c = 0; c < 16; c++) {
        if (c <= 13) cp_wait<2>();
        else if (c == 14) cp_wait<1>();
        else cp_wait<0>();
        __syncthreads();
        if (c + 3 < 16) issue(c + 3);

        const uint32_t stage_addr = smem_base + (uint32_t)((c & 3) * STAGE_W) * 4u;

#pragma unroll
        for (int step = 0; step < 2; step++) {
            const uint32_t so = stage_addr + (uint32_t)(step * 8) * 4u;
            uint32_t a[4][4];
#pragma unroll
            for (int i = 0; i < 4; i++)
                ldm_x4(a[i], so + (a_off + (uint32_t)(i * 16 * PW)) * 4u);
#pragma unroll
            for (int jj = 0; jj < 2; jj++) {
                uint32_t b[4];
                ldm_x4(b, so + (b_off + (uint32_t)(jj * 16 * PW)) * 4u);
#pragma unroll
                for (int i = 0; i < 4; i++) {
                    mma_f16(acc[i][2 * jj    ], a[i], b[0], b[1]);
                    mma_f16(acc[i][2 * jj + 1], a[i], b[2], b[3]);
                }
            }
        }
    }

    // Epilogue: +bias fp32, pack half2, scatter [bw][h][t][d].
#pragma unroll
    for (int i = 0; i < 4; i++) {
        const int m0 = mb + wm + i * 16 + g;
#pragma unroll
        for (int j = 0; j < 4; j++) {
            const int col = nw0 + wn + j * 8 + tig * 2;
            const float bv0 = bias[col], bv1 = bias[col + 1];
            const int h = col >> 6, d = col & 63;
            {
                const int m = m0;
                size_t o = (((size_t)(m >> 6) * 8 + h) * 64 + (m & 63)) * 64 + d;
                *(uint32_t*)&dst[o] = pack2(acc[i][j][0] + bv0, acc[i][j][1] + bv1);
            }
            {
                const int m = m0 + 8;
                size_t o = (((size_t)(m >> 6) * 8 + h) * 64 + (m & 63)) * 64 + d;
                *(uint32_t*)&dst[o] = pack2(acc[i][j][2] + bv0, acc[i][j][3] + bv1);
            }
        }
    }
}

// ---------------------------------------------------------------------------
// Kernel B: per-(window, head) attention, fp16 mma + ldmatrix.x4.
// 4096 CTAs x 128 threads. Q/K/V fp16 [t][d], pitch 36 words.
// ---------------------------------------------------------------------------
#define APITCH 36

__global__ void __launch_bounds__(128) attn_kernel(
    const float* __restrict__ Bbias, float* __restrict__ out)
{
    __shared__ uint32_t qp_s[64 * APITCH];   // Q, later P (warp-private rows)
    __shared__ uint32_t k_s [64 * APITCH];
    __shared__ uint32_t v_s [64 * APITCH];   // [t][d] row-major

    const int tid  = threadIdx.x;
    const int warp = tid >> 5, lane = tid & 31;
    const int g = lane >> 2, tig = lane & 3;
    const int l8 = lane >> 3, r8 = lane & 7;
    const int wh = blockIdx.x;
    const int h  = wh & 7;
    const int bw = wh >> 3;
    const size_t base = (size_t)wh * 4096;

    const uint4* q4 = (const uint4*)(g_qkv + base);
    const uint4* k4 = (const uint4*)(g_qkv + QKV_SZ + base);
    const uint4* v4 = (const uint4*)(g_qkv + 2u * QKV_SZ + base);

#pragma unroll
    for (int i = 0; i < 4; i++) {
        const int c = i * 128 + tid;
        const int t = c >> 3, w4 = (c & 7) * 4;
        *(uint4*)&qp_s[t * APITCH + w4] = q4[c];
        *(uint4*)&k_s [t * APITCH + w4] = k4[c];
        *(uint4*)&v_s [t * APITCH + w4] = v4[c];
    }
    __syncthreads();

    const int qr = warp * 16;
    const uint32_t qp_base = (uint32_t)__cvta_generic_to_shared(qp_s);
    const uint32_t k_base  = (uint32_t)__cvta_generic_to_shared(k_s);
    const uint32_t v_base  = (uint32_t)__cvta_generic_to_shared(v_s);

    const uint32_t aq_off = (uint32_t)((qr + (l8 & 1) * 8 + r8) * APITCH + (l8 >> 1) * 4);
    const uint32_t bk_off = (uint32_t)(((l8 >> 1) * 8 + r8) * APITCH + (l8 & 1) * 4);
    const uint32_t bv_off = (uint32_t)(((l8 & 1) * 8 + r8) * APITCH + (l8 >> 1) * 4);

    // ---- S = Q K^T ----
    float s[8][4];
#pragma unroll
    for (int j = 0; j < 8; j++)
#pragma unroll
        for (int c = 0; c < 4; c++) s[j][c] = 0.f;

#pragma unroll
    for (int kk = 0; kk < 4; kk++) {
        uint32_t a[4];
        ldm_x4(a, qp_base + (aq_off + (uint32_t)(kk * 8)) * 4u);
#pragma unroll
        for (int jj = 0; jj < 4; jj++) {
            uint32_t b[4];
            ldm_x4(b, k_base + (bk_off + (uint32_t)(jj * 16 * APITCH + kk * 8)) * 4u);
            mma_f16(s[2 * jj    ], a, b[0], b[1]);
            mma_f16(s[2 * jj + 1], a, b[2], b[3]);
        }
    }

    // ---- scale + bias + softmax ----
    const float scale = 0.125f;
    float mx0 = -1e30f, mx1 = -1e30f;
#pragma unroll
    for (int j = 0; j < 8; j++) {
        float2 b0 = *(const float2*)&Bbias[(qr + g    ) * 64 + j * 8 + tig * 2];
        float2 b1 = *(const float2*)&Bbias[(qr + g + 8) * 64 + j * 8 + tig * 2];
        s[j][0] = s[j][0] * scale + b0.x;
        s[j][1] = s[j][1] * scale + b0.y;
        s[j][2] = s[j][2] * scale + b1.x;
        s[j][3] = s[j][3] * scale + b1.y;
        mx0 = fmaxf(mx0, fmaxf(s[j][0], s[j][1]));
        mx1 = fmaxf(mx1, fmaxf(s[j][2], s[j][3]));
    }
    mx0 = fmaxf(mx0, __shfl_xor_sync(0xffffffffu, mx0, 1));
    mx0 = fmaxf(mx0, __shfl_xor_sync(0xffffffffu, mx0, 2));
    mx1 = fmaxf(mx1, __shfl_xor_sync(0xffffffffu, mx1, 1));
    mx1 = fmaxf(mx1, __shfl_xor_sync(0xffffffffu, mx1, 2));

    float sum0 = 0.f, sum1 = 0.f;
#pragma unroll
    for (int j = 0; j < 8; j++) {
        s[j][0] = __expf(s[j][0] - mx0);
        s[j][1] = __expf(s[j][1] - mx0);
        s[j][2] = __expf(s[j][2] - mx1);
        s[j][3] = __expf(s[j][3] - mx1);
        sum0 += s[j][0] + s[j][1];
        sum1 += s[j][2] + s[j][3];
    }
    sum0 += __shfl_xor_sync(0xffffffffu, sum0, 1);
    sum0 += __shfl_xor_sync(0xffffffffu, sum0, 2);
    sum1 += __shfl_xor_sync(0xffffffffu, sum1, 1);
    sum1 += __shfl_xor_sync(0xffffffffu, sum1, 2);
    const float inv0 = 1.0f / sum0, inv1 = 1.0f / sum1;

    // ---- P (fp16) over Q smem ----
    __syncwarp();
#pragma unroll
    for (int j = 0; j < 8; j++) {
        qp_s[(qr + g    ) * APITCH + j * 4 + tig] = pack2(s[j][0] * inv0, s[j][1] * inv0);
        qp_s[(qr + g + 8) * APITCH + j * 4 + tig] = pack2(s[j][2] * inv1, s[j][3] * inv1);
    }
    __syncwarp();

    // ---- O = P V ----
    float o[8][4];
#pragma unroll
    for (int j = 0; j < 8; j++)
#pragma unroll
        for (int c = 0; c < 4; c++) o[j][c] = 0.f;

#pragma unroll
    for (int kk = 0; kk < 4; kk++) {
        uint32_t a[4];
        ldm_x4(a, qp_base + (aq_off + (uint32_t)(kk * 8)) * 4u);
#pragma unroll
        for (int jj = 0; jj < 4; jj++) {
            uint32_t b[4];
            ldm_x4_trans(b, v_base + (bv_off + (uint32_t)(kk * 16 * APITCH + jj * 8)) * 4u);
            mma_f16(o[2 * jj    ], a, b[0], b[1]);
            mma_f16(o[2 * jj + 1], a, b[2], b[3]);
        }
    }

    // ---- output ----
    float* o0 = out + ((size_t)bw * 64 + qr + g) * 512 + h * 64;
    float* o1 = o0 + 8 * 512;
#pragma unroll
    for (int j = 0; j < 8; j++) {
        *(float2*)&o0[j * 8 + tig * 2] = make_float2(o[j][0], o[j][1]);
        *(float2*)&o1[j * 8 + tig * 2] = make_float2(o[j][2], o[j][3]);
    }
}

// ---------------------------------------------------------------------------
extern "C" void kernel_launch(void* const* d_in, const int* in_sizes, int n_in,
                              void* d_out, int out_size)
{
    const float* x  = (const float*)d_in[0];
    const float* Wq = (const float*)d_in[1];
    const float* bq = (const float*)d_in[2];
    const float* Wk = (const float*)d_in[3];
    const float* bk = (const float*)d_in[4];
    const float* Wv = (const float*)d_in[5];
    const float* bv = (const float*)d_in[6];
    const float* Bb = (const float*)d_in[7];
    float* out = (float*)d_out;

    cudaFuncSetAttribute(qkv_proj_kernel, cudaFuncAttributeMaxDynamicSharedMemorySize,
                         PROJ_SMEM);

    conv_x_kernel<<<8192, 256>>>(x);
    conv_w_kernel<<<384, 256>>>(Wq, Wk, Wv);

    dim3 gA(12, 256);
    qkv_proj_kernel<<<gA, 256, PROJ_SMEM>>>(bq, bk, bv);

    attn_kernel<<<4096, 128>>>(Bb, out);
}